// round 5
// baseline (speedup 1.0000x reference)
#include <cuda_runtime.h>

// quadLayer: out[b,h,w, c*512 + a*32 + f] =
//   sum_m p[a][m] W1[c][m][f] + sum_{m1,m2} p[a][m1] p[a][m2] W2[c][m1*4+m2][f]
// p[a][mm] = x[b, 2h+((a>>2)>>1), 2w+((a>>2)&1), 4*(a&3)+mm]  (one float4 of x).
//
// R5: symmetrized 14-feature form (R4) + f-pair f32x2 packing:
// thread = (pixpar, c, f4) owns 4 consecutive f -> one STG.128 per (pix,a).
// Features stored DUPLICATED in smem: LDS.128 -> two {v,v} f32x2 operands.
// Weights packed {w[f],w[f+1]} in regs (28 u64). 3 CTAs/SM target.

#define NPIX 16
#define THREADS 256
#define NK 14
#define ABYTES (NK * 8)   // 112 B per (pix, a): 14 duplicated pairs

__device__ __forceinline__ void fma2(unsigned long long &d,
                                     unsigned long long a,
                                     unsigned long long b) {
    asm("fma.rn.f32x2 %0, %1, %2, %0;" : "+l"(d) : "l"(a), "l"(b));
}

__device__ __forceinline__ unsigned long long packw(const float* base, int idx) {
    unsigned long long r;
    float lo = base[idx], hi = base[idx + 1];
    asm("mov.b64 %0, {%1,%2};" : "=l"(r) : "f"(lo), "f"(hi));
    return r;
}

__global__ void __launch_bounds__(THREADS, 3)
quad_kernel(const float* __restrict__ x,
            const float* __restrict__ W1,
            const float* __restrict__ W2,
            float* __restrict__ out)
{
    // NPIX * 16 a * 14 k * 2 (dup) floats = 28 KB
    __shared__ __align__(16) float feat[NPIX * 16 * NK * 2];

    const int t      = threadIdx.x;
    const int pixpar = t >> 7;        // 0..1
    const int c      = (t >> 3) & 15; // 0..15
    const int f4     = t & 7;         // 0..7 -> f = 4*f4 .. 4*f4+3
    const int f0     = f4 * 4;

    // ---- symmetrized weights, packed over f: wp0={f0,f0+1}, wp1={f0+2,f0+3} ----
    unsigned long long wp0[NK], wp1[NK];
    {
        const float* w1c = W1 + c * 128 + f0;
        const float* w2c = W2 + c * 512 + f0;
#pragma unroll
        for (int m = 0; m < 4; m++) {          // linear
            wp0[m] = packw(w1c, m * 32);
            wp1[m] = packw(w1c, m * 32 + 2);
        }
#pragma unroll
        for (int m = 0; m < 4; m++) {          // squares (diag q = 5m)
            wp0[4 + m] = packw(w2c, (5 * m) * 32);
            wp1[4 + m] = packw(w2c, (5 * m) * 32 + 2);
        }
        int k = 8;                             // cross terms, m1 < m2 (folded)
#pragma unroll
        for (int m1 = 0; m1 < 4; m1++)
#pragma unroll
            for (int m2 = m1 + 1; m2 < 4; m2++) {
                const int qa = (m1 * 4 + m2) * 32, qb = (m2 * 4 + m1) * 32;
                float a0 = w2c[qa] + w2c[qb];
                float a1 = w2c[qa + 1] + w2c[qb + 1];
                float a2 = w2c[qa + 2] + w2c[qb + 2];
                float a3 = w2c[qa + 3] + w2c[qb + 3];
                asm("mov.b64 %0, {%1,%2};" : "=l"(wp0[k]) : "f"(a0), "f"(a1));
                asm("mov.b64 %0, {%1,%2};" : "=l"(wp1[k]) : "f"(a2), "f"(a3));
                k++;
            }
    }

    // ---- feature build: one thread per (pix, a); values duplicated ----
    {
        const int pix = t >> 4;
        const int a   = t & 15;
        const int g   = blockIdx.x * NPIX + pix;   // global pixel id
        const int b   = g >> 10;
        const int h   = (g >> 5) & 31;
        const int wc  = g & 31;
        const int m   = a >> 2;
        const int i   = m >> 1;
        const int j   = m & 1;
        const int ch0 = (a & 3) * 4;
        const float4 v = *reinterpret_cast<const float4*>(
            x + (((b * 64 + 2 * h + i) * 64) + (2 * wc + j)) * 16 + ch0);
        const float p[4] = {v.x, v.y, v.z, v.w};
        float* fb = &feat[(pix * 16 + a) * (NK * 2)];
#pragma unroll
        for (int k = 0; k < 4; k++) { fb[2 * k] = p[k]; fb[2 * k + 1] = p[k]; }
#pragma unroll
        for (int m0 = 0; m0 < 4; m0++) {
            const float s = p[m0] * p[m0];
            fb[2 * (4 + m0)] = s; fb[2 * (4 + m0) + 1] = s;
        }
        int k = 8;
#pragma unroll
        for (int m1 = 0; m1 < 4; m1++)
#pragma unroll
            for (int m2 = m1 + 1; m2 < 4; m2++) {
                const float s = p[m1] * p[m2];
                fb[2 * k] = s; fb[2 * k + 1] = s;
                k++;
            }
    }
    __syncthreads();

    const size_t gbase = (size_t)blockIdx.x * NPIX * 8192
                       + (size_t)(c * 512 + f0);
    const unsigned int sbase = (unsigned int)__cvta_generic_to_shared(feat);

#pragma unroll 1
    for (int pp = 0; pp < NPIX / 2; pp++) {
        const int pix = 2 * pp + pixpar;
        const size_t obase = gbase + (size_t)pix * 8192;
        const unsigned int pbase = sbase + pix * (16 * ABYTES);
#pragma unroll 2
        for (int a = 0; a < 16; a++) {
            const unsigned int addr = pbase + a * ABYTES;
            unsigned long long acc0 = 0, acc1 = 0, bcc0 = 0, bcc1 = 0;
            // half 1: k = 0..7 (4 LDS.128 -> 8 dup-pairs)
            {
                unsigned long long fp[8];
#pragma unroll
                for (int q = 0; q < 4; q++)
                    asm("ld.shared.v2.u64 {%0,%1}, [%2];"
                        : "=l"(fp[2 * q]), "=l"(fp[2 * q + 1])
                        : "r"(addr + q * 16));
#pragma unroll
                for (int k = 0; k < 8; k += 2) {
                    fma2(acc0, wp0[k],     fp[k]);
                    fma2(acc1, wp1[k],     fp[k]);
                    fma2(bcc0, wp0[k + 1], fp[k + 1]);
                    fma2(bcc1, wp1[k + 1], fp[k + 1]);
                }
            }
            // half 2: k = 8..13 (3 LDS.128 -> 6 dup-pairs)
            {
                unsigned long long fp[6];
#pragma unroll
                for (int q = 0; q < 3; q++)
                    asm("ld.shared.v2.u64 {%0,%1}, [%2];"
                        : "=l"(fp[2 * q]), "=l"(fp[2 * q + 1])
                        : "r"(addr + 64 + q * 16));
#pragma unroll
                for (int k = 0; k < 6; k += 2) {
                    fma2(acc0, wp0[8 + k],     fp[k]);
                    fma2(acc1, wp1[8 + k],     fp[k]);
                    fma2(bcc0, wp0[8 + k + 1], fp[k + 1]);
                    fma2(bcc1, wp1[8 + k + 1], fp[k + 1]);
                }
            }
            unsigned long long s0, s1;
            asm("add.rn.f32x2 %0, %1, %2;" : "=l"(s0) : "l"(acc0), "l"(bcc0));
            asm("add.rn.f32x2 %0, %1, %2;" : "=l"(s1) : "l"(acc1), "l"(bcc1));
            float r0, r1, r2, r3;
            asm("mov.b64 {%0,%1}, %2;" : "=f"(r0), "=f"(r1) : "l"(s0));
            asm("mov.b64 {%0,%1}, %2;" : "=f"(r2), "=f"(r3) : "l"(s1));
            asm("st.global.cs.v4.f32 [%0], {%1,%2,%3,%4};"
                :: "l"(out + obase + (size_t)(a * 32)),
                   "f"(r0), "f"(r1), "f"(r2), "f"(r3) : "memory");
        }
    }
}

extern "C" void kernel_launch(void* const* d_in, const int* in_sizes, int n_in,
                              void* d_out, int out_size) {
    const float* x  = (const float*)d_in[0];
    const float* W1 = (const float*)d_in[1];
    const float* W2 = (const float*)d_in[2];
    float* out = (float*)d_out;
    quad_kernel<<<8192 / NPIX, THREADS>>>(x, W1, W2, out);
}

// round 6
// speedup vs baseline: 1.2829x; 1.2829x over previous
#include <cuda_runtime.h>

// quadLayer: out[b,h,w, c*512 + a*32 + f] =
//   sum_m p[a][m] W1[c][m][f] + sum_{m1,m2} p[a][m1] p[a][m2] W2[c][m1*4+m2][f]
// p[a][mm] = x[b, 2h+((a>>2)>>1), 2w+((a>>2)&1), 4*(a&3)+mm]  (one float4 of x).
//
// R6: Horner form of the symmetric quadratic:
//   t[m1] = W1[m1] + sum_{m2>=m1} p[m2] * W2s[m1][m2]
//   out   = sum_{m1} p[m1] * t[m1]
// with W2s[m,m]=W2[5m], W2s[m1,m2]=W2[m1*4+m2]+W2[m2*4+m1] (m1<m2).
// Only the 4 base p values are loaded per (pix, a-pair) — 2 LDS.128 of
// a-parity-packed f32x2 pairs. 2 c-planes per thread; all math fma.rn.f32x2.

#define NPIX 16
#define THREADS 256

__device__ __forceinline__ unsigned long long pack2(float lo, float hi) {
    unsigned long long r;
    asm("mov.b64 %0, {%1,%2};" : "=l"(r) : "f"(lo), "f"(hi));
    return r;
}

// d += a*b
__device__ __forceinline__ void fma2(unsigned long long &d,
                                     unsigned long long a,
                                     unsigned long long b) {
    asm("fma.rn.f32x2 %0, %1, %2, %0;" : "+l"(d) : "l"(a), "l"(b));
}

// d = a*b + c
__device__ __forceinline__ unsigned long long fma2n(unsigned long long a,
                                                    unsigned long long b,
                                                    unsigned long long c) {
    unsigned long long d;
    asm("fma.rn.f32x2 %0, %1, %2, %3;" : "=l"(d) : "l"(a), "l"(b), "l"(c));
    return d;
}

// d = a*b
__device__ __forceinline__ unsigned long long mul2(unsigned long long a,
                                                   unsigned long long b) {
    unsigned long long d;
    asm("mul.rn.f32x2 %0, %1, %2;" : "=l"(d) : "l"(a), "l"(b));
    return d;
}

__device__ __forceinline__ unsigned long long add2(unsigned long long a,
                                                   unsigned long long b) {
    unsigned long long r;
    asm("add.rn.f32x2 %0, %1, %2;" : "=l"(r) : "l"(a), "l"(b));
    return r;
}

__global__ void __launch_bounds__(THREADS, 2)
quad_kernel(const float* __restrict__ x,
            const float* __restrict__ W1,
            const float* __restrict__ W2,
            float* __restrict__ out)
{
    // base values only: NPIX * 8 ap * 4 m * 2 parity floats = 4 KB
    __shared__ __align__(16) float pbase[NPIX * 8 * 4 * 2];

    const int t  = threadIdx.x;
    const int c0 = t >> 5;   // 0..7  (planes c0 and c0+8)
    const int f  = t & 31;   // 0..31

    // ---- weights (duplicated f32x2), Horner layout ----
    // lin[m] = W1[c][m][f]; q[m1][m2] (m1<=m2) = W2s[m1][m2]
    unsigned long long linA[4], linB[4], qA[10], qB[10];
    {
        const int cA = c0, cB = c0 + 8;
        const float* w1a = W1 + cA * 128 + f;
        const float* w1b = W1 + cB * 128 + f;
        const float* w2a = W2 + cA * 512 + f;
        const float* w2b = W2 + cB * 512 + f;
#pragma unroll
        for (int m = 0; m < 4; m++) {
            float a = w1a[m * 32], b = w1b[m * 32];
            linA[m] = pack2(a, a);
            linB[m] = pack2(b, b);
        }
        int k = 0;
#pragma unroll
        for (int m1 = 0; m1 < 4; m1++)
#pragma unroll
            for (int m2 = m1; m2 < 4; m2++) {
                float a, b;
                if (m1 == m2) {
                    a = w2a[(5 * m1) * 32];
                    b = w2b[(5 * m1) * 32];
                } else {
                    a = w2a[(m1 * 4 + m2) * 32] + w2a[(m2 * 4 + m1) * 32];
                    b = w2b[(m1 * 4 + m2) * 32] + w2b[(m2 * 4 + m1) * 32];
                }
                qA[k] = pack2(a, a);
                qB[k] = pack2(b, b);
                k++;
            }
    }

    // ---- base-value build: one thread per (pix, a) ----
    {
        const int pix = t >> 4;
        const int a   = t & 15;
        const int g   = blockIdx.x * NPIX + pix;   // global pixel id
        const int b   = g >> 10;
        const int h   = (g >> 5) & 31;
        const int wc  = g & 31;
        const int m   = a >> 2;
        const int i   = m >> 1;
        const int j   = m & 1;
        const int ch0 = (a & 3) * 4;
        const float4 v = *reinterpret_cast<const float4*>(
            x + (((b * 64 + 2 * h + i) * 64) + (2 * wc + j)) * 16 + ch0);
        float* fb = &pbase[(pix * 8 + (a >> 1)) * 8 + (a & 1)];
        fb[0] = v.x; fb[2] = v.y; fb[4] = v.z; fb[6] = v.w;
    }
    __syncthreads();

    const size_t gbase = (size_t)blockIdx.x * NPIX * 8192 + (size_t)f;
    const int offA = c0 * 512;
    const int offB = (c0 + 8) * 512;
    const unsigned int sbase = (unsigned int)__cvta_generic_to_shared(pbase);

#pragma unroll 1
    for (int pix = 0; pix < NPIX; pix++) {
        const size_t obase = gbase + (size_t)pix * 8192;
        const unsigned int pb = sbase + pix * (8 * 32);
#pragma unroll
        for (int ap = 0; ap < 8; ap++) {
            unsigned long long pp0, pp1, pp2, pp3;
            asm("ld.shared.v2.u64 {%0,%1}, [%2];"
                : "=l"(pp0), "=l"(pp1) : "r"(pb + ap * 32));
            asm("ld.shared.v2.u64 {%0,%1}, [%2];"
                : "=l"(pp2), "=l"(pp3) : "r"(pb + ap * 32 + 16));

            // t[m1] = lin[m1] + sum_{m2>=m1} pp[m2]*q[m1][m2]
            // q index k: (0,0)=0 (0,1)=1 (0,2)=2 (0,3)=3 (1,1)=4 (1,2)=5
            //            (1,3)=6 (2,2)=7 (2,3)=8 (3,3)=9
            unsigned long long tA0 = fma2n(pp0, qA[0], linA[0]);
            unsigned long long tB0 = fma2n(pp0, qB[0], linB[0]);
            unsigned long long tA1 = fma2n(pp1, qA[4], linA[1]);
            unsigned long long tB1 = fma2n(pp1, qB[4], linB[1]);
            unsigned long long tA2 = fma2n(pp2, qA[7], linA[2]);
            unsigned long long tB2 = fma2n(pp2, qB[7], linB[2]);
            unsigned long long tA3 = fma2n(pp3, qA[9], linA[3]);
            unsigned long long tB3 = fma2n(pp3, qB[9], linB[3]);
            fma2(tA0, pp1, qA[1]);  fma2(tB0, pp1, qB[1]);
            fma2(tA1, pp2, qA[5]);  fma2(tB1, pp2, qB[5]);
            fma2(tA2, pp3, qA[8]);  fma2(tB2, pp3, qB[8]);
            fma2(tA0, pp2, qA[2]);  fma2(tB0, pp2, qB[2]);
            fma2(tA1, pp3, qA[6]);  fma2(tB1, pp3, qB[6]);
            fma2(tA0, pp3, qA[3]);  fma2(tB0, pp3, qB[3]);

            // out = sum pp[m]*t[m]  (two chains, then add)
            unsigned long long sA0 = mul2(pp0, tA0);
            unsigned long long sB0 = mul2(pp0, tB0);
            unsigned long long sA1 = mul2(pp1, tA1);
            unsigned long long sB1 = mul2(pp1, tB1);
            fma2(sA0, pp2, tA2);  fma2(sB0, pp2, tB2);
            fma2(sA1, pp3, tA3);  fma2(sB1, pp3, tB3);
            const unsigned long long sA = add2(sA0, sA1);
            const unsigned long long sB = add2(sB0, sB1);

            float lA, hA, lB, hB;
            asm("mov.b64 {%0,%1}, %2;" : "=f"(lA), "=f"(hA) : "l"(sA));
            asm("mov.b64 {%0,%1}, %2;" : "=f"(lB), "=f"(hB) : "l"(sB));
            out[obase + (size_t)(offA + (2 * ap) * 32)]     = lA;
            out[obase + (size_t)(offA + (2 * ap + 1) * 32)] = hA;
            out[obase + (size_t)(offB + (2 * ap) * 32)]     = lB;
            out[obase + (size_t)(offB + (2 * ap + 1) * 32)] = hB;
        }
    }
}

extern "C" void kernel_launch(void* const* d_in, const int* in_sizes, int n_in,
                              void* d_out, int out_size) {
    const float* x  = (const float*)d_in[0];
    const float* W1 = (const float*)d_in[1];
    const float* W2 = (const float*)d_in[2];
    float* out = (float*)d_out;
    quad_kernel<<<8192 / NPIX, THREADS>>>(x, W1, W2, out);
}